// round 2
// baseline (speedup 1.0000x reference)
#include <cuda_runtime.h>
#include <cstdint>

typedef unsigned long long u64;

// ---------------- f32x2 packed-fp32 helpers (Blackwell FFMA2 path) -----------
__device__ __forceinline__ u64 ffma2(u64 a, u64 b, u64 c) {
    u64 d;
    asm("fma.rn.f32x2 %0, %1, %2, %3;" : "=l"(d) : "l"(a), "l"(b), "l"(c));
    return d;
}
__device__ __forceinline__ u64 pack2(float lo, float hi) {
    u64 r;
    asm("mov.b64 %0, {%1, %2};" : "=l"(r) : "f"(lo), "f"(hi));
    return r;
}
__device__ __forceinline__ float2 unpack2(u64 v) {
    float2 f;
    asm("mov.b64 {%0, %1}, %2;" : "=f"(f.x), "=f"(f.y) : "l"(v));
    return f;
}

// =============================================================================
// Phase 1: x_proj GEMM.  out[row, j] = bias[j] + sum_k X[row,k] * W[j,k]
// X: [131072, 256], W row stride 512 (W_x = first 256 cols), out: [131072, 256]
// 128x128 tile, BK=16, 256 threads, 8x8 microtile, f32x2 accumulators.
// =============================================================================
__global__ __launch_bounds__(256, 2) void xproj_gemm(
    const float* __restrict__ X, const float* __restrict__ W,
    const float* __restrict__ bias, float* __restrict__ out)
{
    __shared__ float As[2][16][128];
    __shared__ float Bs[2][16][128];

    const int tid   = threadIdx.x;
    const int mBase = blockIdx.x * 128;
    const int nBase = blockIdx.y * 128;

    const int lrow = tid & 127;
    const int lkg0 = tid >> 7;              // 0 or 1

    const float* Aptr = X + (size_t)(mBase + lrow) * 256;
    const float* Bptr = W + (size_t)(nBase + lrow) * 512;

    const int tx = tid & 15;
    const int ty = tid >> 4;
    const int j0 = tx * 8;
    const int r0 = ty * 8;

    u64 acc[4][8];
    #pragma unroll
    for (int ri = 0; ri < 4; ri++)
        #pragma unroll
        for (int j = 0; j < 8; j++) acc[ri][j] = 0ull;

    // ---- prologue: load k-tile 0 into buffer 0 ----
    {
        float4 av0 = *(const float4*)(Aptr + lkg0 * 4);
        float4 av1 = *(const float4*)(Aptr + (lkg0 + 2) * 4);
        float4 bv0 = *(const float4*)(Bptr + lkg0 * 4);
        float4 bv1 = *(const float4*)(Bptr + (lkg0 + 2) * 4);
        const int ka = lkg0 * 4, kb = (lkg0 + 2) * 4;
        As[0][ka+0][lrow] = av0.x; As[0][ka+1][lrow] = av0.y;
        As[0][ka+2][lrow] = av0.z; As[0][ka+3][lrow] = av0.w;
        As[0][kb+0][lrow] = av1.x; As[0][kb+1][lrow] = av1.y;
        As[0][kb+2][lrow] = av1.z; As[0][kb+3][lrow] = av1.w;
        Bs[0][ka+0][lrow] = bv0.x; Bs[0][ka+1][lrow] = bv0.y;
        Bs[0][ka+2][lrow] = bv0.z; Bs[0][ka+3][lrow] = bv0.w;
        Bs[0][kb+0][lrow] = bv1.x; Bs[0][kb+1][lrow] = bv1.y;
        Bs[0][kb+2][lrow] = bv1.z; Bs[0][kb+3][lrow] = bv1.w;
    }
    __syncthreads();

    #pragma unroll 1
    for (int kt = 0; kt < 16; kt++) {
        const int cur = kt & 1;
        float4 na0, na1, nb0, nb1;
        if (kt < 15) {
            const float* ap = Aptr + (kt + 1) * 16;
            const float* bp = Bptr + (kt + 1) * 16;
            na0 = *(const float4*)(ap + lkg0 * 4);
            na1 = *(const float4*)(ap + (lkg0 + 2) * 4);
            nb0 = *(const float4*)(bp + lkg0 * 4);
            nb1 = *(const float4*)(bp + (lkg0 + 2) * 4);
        }
        #pragma unroll
        for (int k = 0; k < 16; k++) {
            float4 a0 = *(const float4*)&As[cur][k][r0];
            float4 a1 = *(const float4*)&As[cur][k][r0 + 4];
            float4 b0 = *(const float4*)&Bs[cur][k][j0];
            float4 b1 = *(const float4*)&Bs[cur][k][j0 + 4];
            u64 aa[4];
            aa[0] = pack2(a0.x, a0.y); aa[1] = pack2(a0.z, a0.w);
            aa[2] = pack2(a1.x, a1.y); aa[3] = pack2(a1.z, a1.w);
            float bsv[8] = {b0.x, b0.y, b0.z, b0.w, b1.x, b1.y, b1.z, b1.w};
            #pragma unroll
            for (int j = 0; j < 8; j++) {
                u64 bb = pack2(bsv[j], bsv[j]);
                #pragma unroll
                for (int ri = 0; ri < 4; ri++)
                    acc[ri][j] = ffma2(aa[ri], bb, acc[ri][j]);
            }
        }
        if (kt < 15) {
            const int nxt = cur ^ 1;
            const int ka = lkg0 * 4, kb = (lkg0 + 2) * 4;
            As[nxt][ka+0][lrow] = na0.x; As[nxt][ka+1][lrow] = na0.y;
            As[nxt][ka+2][lrow] = na0.z; As[nxt][ka+3][lrow] = na0.w;
            As[nxt][kb+0][lrow] = na1.x; As[nxt][kb+1][lrow] = na1.y;
            As[nxt][kb+2][lrow] = na1.z; As[nxt][kb+3][lrow] = na1.w;
            Bs[nxt][ka+0][lrow] = nb0.x; Bs[nxt][ka+1][lrow] = nb0.y;
            Bs[nxt][ka+2][lrow] = nb0.z; Bs[nxt][ka+3][lrow] = nb0.w;
            Bs[nxt][kb+0][lrow] = nb1.x; Bs[nxt][kb+1][lrow] = nb1.y;
            Bs[nxt][kb+2][lrow] = nb1.z; Bs[nxt][kb+3][lrow] = nb1.w;
        }
        __syncthreads();
    }

    // ---- epilogue: add bias, store ----
    float bvv[8];
    *(float4*)&bvv[0] = *(const float4*)(bias + nBase + j0);
    *(float4*)&bvv[4] = *(const float4*)(bias + nBase + j0 + 4);
    #pragma unroll
    for (int ri = 0; ri < 4; ri++) {
        float lo[8], hi[8];
        #pragma unroll
        for (int j = 0; j < 8; j++) {
            float2 f = unpack2(acc[ri][j]);
            lo[j] = f.x + bvv[j];
            hi[j] = f.y + bvv[j];
        }
        float* orow0 = out + (size_t)(mBase + r0 + 2 * ri) * 256 + nBase + j0;
        float* orow1 = orow0 + 256;
        *(float4*)(orow0)     = make_float4(lo[0], lo[1], lo[2], lo[3]);
        *(float4*)(orow0 + 4) = make_float4(lo[4], lo[5], lo[6], lo[7]);
        *(float4*)(orow1)     = make_float4(hi[0], hi[1], hi[2], hi[3]);
        *(float4*)(orow1 + 4) = make_float4(hi[4], hi[5], hi[6], hi[7]);
    }
}

// =============================================================================
// Phase 2: sequential recurrence, one CTA per batch, 512 threads.
//   out[b,t,:] = xproj[b,t,:] + W_h @ h_prev      (in place: out holds xproj)
// W_h = W[:, 256:512].  Weights: 52 float2/thread in registers (104 regs),
// 12 float2/thread residual in SMEM.  h kept as packed float2 in SMEM with
// 17-pair chunk stride (bank-conflict-free broadcast reads).
// Thread (q = tid&7, jset = tid>>3) covers outputs jset*4..+3, k-chunk q*32..+31.
// =============================================================================
__global__ __launch_bounds__(512, 1) void rnn_scan(
    const float* __restrict__ W, const float* __restrict__ hidden,
    float* __restrict__ out)
{
    extern __shared__ u64 dynsm[];
    u64*   resw = dynsm;                    // [12][512] u64          (49152 B)
    float* part = (float*)(dynsm + 6144);   // [256*9] floats          (9216 B)
    u64*   h2   = dynsm + 7296;             // [2][8*17] u64 (padded)  (2176 B)

    const int tid  = threadIdx.x;
    const int b    = blockIdx.x;
    const int q    = tid & 7;
    const int jset = tid >> 3;

    // ---- load weights: 13 reg pairs + 3 residual pairs per (output, chunk) ----
    u64 w[4][13];
    #pragma unroll
    for (int u = 0; u < 4; u++) {
        const u64* wr = (const u64*)(W + (size_t)(jset * 4 + u) * 512 + 256);
        #pragma unroll
        for (int i = 0; i < 13; i++) w[u][i] = wr[q * 16 + i];
        #pragma unroll
        for (int ir = 0; ir < 3; ir++)
            resw[(u * 3 + ir) * 512 + tid] = wr[q * 16 + 13 + ir];
    }

    // ---- init h (buffer 0) from `hidden` input ----
    if (tid < 128) {
        u64 hv = ((const u64*)(hidden + b * 256))[tid];
        h2[(tid >> 4) * 17 + (tid & 15)] = hv;
    }

    // ---- prefetch xproj[b,0,tid] (xproj staged in `out`) ----
    float xpre = 0.f;
    float* outp = out + (size_t)b * 2048 * 256 + tid;
    if (tid < 256) xpre = *outp;

    __syncthreads();

    const u64* rw = resw + tid;

    #pragma unroll 1
    for (int t = 0; t < 2048; t++) {
        const u64* hb = h2 + (t & 1) * 136 + q * 17;
        u64 a0 = 0, a1 = 0, a2 = 0, a3 = 0;
        #pragma unroll
        for (int i = 0; i < 13; i++) {
            u64 hh = hb[i];
            a0 = ffma2(w[0][i], hh, a0);
            a1 = ffma2(w[1][i], hh, a1);
            a2 = ffma2(w[2][i], hh, a2);
            a3 = ffma2(w[3][i], hh, a3);
        }
        #pragma unroll
        for (int ir = 0; ir < 3; ir++) {
            u64 hh = hb[13 + ir];
            a0 = ffma2(rw[(0 * 3 + ir) * 512], hh, a0);
            a1 = ffma2(rw[(1 * 3 + ir) * 512], hh, a1);
            a2 = ffma2(rw[(2 * 3 + ir) * 512], hh, a2);
            a3 = ffma2(rw[(3 * 3 + ir) * 512], hh, a3);
        }
        float2 f0 = unpack2(a0), f1 = unpack2(a1), f2 = unpack2(a2), f3 = unpack2(a3);
        const int pb = (jset * 4) * 9 + q;
        part[pb]      = f0.x + f0.y;
        part[pb + 9]  = f1.x + f1.y;
        part[pb + 18] = f2.x + f2.y;
        part[pb + 27] = f3.x + f3.y;
        __syncthreads();
        if (tid < 256) {
            const float* pr = part + tid * 9;
            float s = ((pr[0] + pr[1]) + (pr[2] + pr[3]))
                    + ((pr[4] + pr[5]) + (pr[6] + pr[7]));
            float hnew = s + xpre;
            int p = tid >> 1;
            float* hw = (float*)(h2 + ((t + 1) & 1) * 136);
            hw[((p >> 4) * 17 + (p & 15)) * 2 + (tid & 1)] = hnew;
            *outp = hnew;
            if (t < 2047) xpre = outp[256];
            outp += 256;
        }
        __syncthreads();
    }
}

// =============================================================================
extern "C" void kernel_launch(void* const* d_in, const int* in_sizes, int n_in,
                              void* d_out, int out_size)
{
    (void)in_sizes; (void)n_in; (void)out_size;
    const float* X      = (const float*)d_in[0];   // input_seq [64,2048,256]
    const float* hidden = (const float*)d_in[1];   // [64,256]
    const float* W      = (const float*)d_in[2];   // [256,512]
    const float* bias   = (const float*)d_in[3];   // [256]
    float* out          = (float*)d_out;           // [64,2048,256]

    // Phase 1: x_proj into d_out (scratch-in-place).
    dim3 g1(1024, 2);
    xproj_gemm<<<g1, 256>>>(X, W, bias, out);

    // Phase 2: sequential scan, 64 CTAs (one per batch), 60544 B dynamic smem.
    cudaFuncSetAttribute(rnn_scan, cudaFuncAttributeMaxDynamicSharedMemorySize, 60544);
    rnn_scan<<<64, 512, 60544>>>(W, hidden, out);
}

// round 4
// speedup vs baseline: 1.6938x; 1.6938x over previous
#include <cuda_runtime.h>
#include <cstdint>

typedef unsigned long long u64;

// ---------------- f32x2 packed-fp32 helpers (Blackwell FFMA2 path) -----------
__device__ __forceinline__ u64 ffma2(u64 a, u64 b, u64 c) {
    u64 d;
    asm("fma.rn.f32x2 %0, %1, %2, %3;" : "=l"(d) : "l"(a), "l"(b), "l"(c));
    return d;
}
__device__ __forceinline__ u64 pack2(float lo, float hi) {
    u64 r;
    asm("mov.b64 %0, {%1, %2};" : "=l"(r) : "f"(lo), "f"(hi));
    return r;
}
__device__ __forceinline__ float2 unpack2(u64 v) {
    float2 f;
    asm("mov.b64 {%0, %1}, %2;" : "=f"(f.x), "=f"(f.y) : "l"(v));
    return f;
}

// =============================================================================
// Phase 1: x_proj GEMM.  out[row, j] = bias[j] + sum_k X[row,k] * W[j,k]
// X: [131072, 256], W row stride 512 (W_x = first 256 cols), out: [131072, 256]
// 128x128 tile, BK=16, 256 threads, 8x8 microtile, f32x2 accumulators.
// =============================================================================
__global__ __launch_bounds__(256, 2) void xproj_gemm(
    const float* __restrict__ X, const float* __restrict__ W,
    const float* __restrict__ bias, float* __restrict__ out)
{
    __shared__ float As[2][16][128];
    __shared__ float Bs[2][16][128];

    const int tid   = threadIdx.x;
    const int mBase = blockIdx.x * 128;
    const int nBase = blockIdx.y * 128;

    const int lrow = tid & 127;
    const int lkg0 = tid >> 7;              // 0 or 1

    const float* Aptr = X + (size_t)(mBase + lrow) * 256;
    const float* Bptr = W + (size_t)(nBase + lrow) * 512;

    const int tx = tid & 15;
    const int ty = tid >> 4;
    const int j0 = tx * 8;
    const int r0 = ty * 8;

    u64 acc[4][8];
    #pragma unroll
    for (int ri = 0; ri < 4; ri++)
        #pragma unroll
        for (int j = 0; j < 8; j++) acc[ri][j] = 0ull;

    // ---- prologue: load k-tile 0 into buffer 0 ----
    {
        float4 av0 = *(const float4*)(Aptr + lkg0 * 4);
        float4 av1 = *(const float4*)(Aptr + (lkg0 + 2) * 4);
        float4 bv0 = *(const float4*)(Bptr + lkg0 * 4);
        float4 bv1 = *(const float4*)(Bptr + (lkg0 + 2) * 4);
        const int ka = lkg0 * 4, kb = (lkg0 + 2) * 4;
        As[0][ka+0][lrow] = av0.x; As[0][ka+1][lrow] = av0.y;
        As[0][ka+2][lrow] = av0.z; As[0][ka+3][lrow] = av0.w;
        As[0][kb+0][lrow] = av1.x; As[0][kb+1][lrow] = av1.y;
        As[0][kb+2][lrow] = av1.z; As[0][kb+3][lrow] = av1.w;
        Bs[0][ka+0][lrow] = bv0.x; Bs[0][ka+1][lrow] = bv0.y;
        Bs[0][ka+2][lrow] = bv0.z; Bs[0][ka+3][lrow] = bv0.w;
        Bs[0][kb+0][lrow] = bv1.x; Bs[0][kb+1][lrow] = bv1.y;
        Bs[0][kb+2][lrow] = bv1.z; Bs[0][kb+3][lrow] = bv1.w;
    }
    __syncthreads();

    #pragma unroll 1
    for (int kt = 0; kt < 16; kt++) {
        const int cur = kt & 1;
        float4 na0, na1, nb0, nb1;
        if (kt < 15) {
            const float* ap = Aptr + (kt + 1) * 16;
            const float* bp = Bptr + (kt + 1) * 16;
            na0 = *(const float4*)(ap + lkg0 * 4);
            na1 = *(const float4*)(ap + (lkg0 + 2) * 4);
            nb0 = *(const float4*)(bp + lkg0 * 4);
            nb1 = *(const float4*)(bp + (lkg0 + 2) * 4);
        }
        #pragma unroll
        for (int k = 0; k < 16; k++) {
            float4 a0 = *(const float4*)&As[cur][k][r0];
            float4 a1 = *(const float4*)&As[cur][k][r0 + 4];
            float4 b0 = *(const float4*)&Bs[cur][k][j0];
            float4 b1 = *(const float4*)&Bs[cur][k][j0 + 4];
            u64 aa[4];
            aa[0] = pack2(a0.x, a0.y); aa[1] = pack2(a0.z, a0.w);
            aa[2] = pack2(a1.x, a1.y); aa[3] = pack2(a1.z, a1.w);
            float bsv[8] = {b0.x, b0.y, b0.z, b0.w, b1.x, b1.y, b1.z, b1.w};
            #pragma unroll
            for (int j = 0; j < 8; j++) {
                u64 bb = pack2(bsv[j], bsv[j]);
                #pragma unroll
                for (int ri = 0; ri < 4; ri++)
                    acc[ri][j] = ffma2(aa[ri], bb, acc[ri][j]);
            }
        }
        if (kt < 15) {
            const int nxt = cur ^ 1;
            const int ka = lkg0 * 4, kb = (lkg0 + 2) * 4;
            As[nxt][ka+0][lrow] = na0.x; As[nxt][ka+1][lrow] = na0.y;
            As[nxt][ka+2][lrow] = na0.z; As[nxt][ka+3][lrow] = na0.w;
            As[nxt][kb+0][lrow] = na1.x; As[nxt][kb+1][lrow] = na1.y;
            As[nxt][kb+2][lrow] = na1.z; As[nxt][kb+3][lrow] = na1.w;
            Bs[nxt][ka+0][lrow] = nb0.x; Bs[nxt][ka+1][lrow] = nb0.y;
            Bs[nxt][ka+2][lrow] = nb0.z; Bs[nxt][ka+3][lrow] = nb0.w;
            Bs[nxt][kb+0][lrow] = nb1.x; Bs[nxt][kb+1][lrow] = nb1.y;
            Bs[nxt][kb+2][lrow] = nb1.z; Bs[nxt][kb+3][lrow] = nb1.w;
        }
        __syncthreads();
    }

    // ---- epilogue: add bias, store ----
    float bvv[8];
    *(float4*)&bvv[0] = *(const float4*)(bias + nBase + j0);
    *(float4*)&bvv[4] = *(const float4*)(bias + nBase + j0 + 4);
    #pragma unroll
    for (int ri = 0; ri < 4; ri++) {
        float lo[8], hi[8];
        #pragma unroll
        for (int j = 0; j < 8; j++) {
            float2 f = unpack2(acc[ri][j]);
            lo[j] = f.x + bvv[j];
            hi[j] = f.y + bvv[j];
        }
        float* orow0 = out + (size_t)(mBase + r0 + 2 * ri) * 256 + nBase + j0;
        float* orow1 = orow0 + 256;
        *(float4*)(orow0)     = make_float4(lo[0], lo[1], lo[2], lo[3]);
        *(float4*)(orow0 + 4) = make_float4(lo[4], lo[5], lo[6], lo[7]);
        *(float4*)(orow1)     = make_float4(hi[0], hi[1], hi[2], hi[3]);
        *(float4*)(orow1 + 4) = make_float4(hi[4], hi[5], hi[6], hi[7]);
    }
}

// =============================================================================
// Phase 2: sequential recurrence, one CTA per batch, 512 threads.
//   out[b,t,:] = xproj[b,t,:] + W_h @ h_prev      (in place: out holds xproj)
// W_h = W[:, 256:512].
// Register/SMEM balance: 11 float2 pairs per output in registers (88 regs)
// + 5 pairs per output streamed from SMEM (20 u64/thread/step).  Total
// register use ~116 < 128 cap -> NO SPILLS (R2 baseline spilled at 128).
// SMEM residual stream = 20 LDS.64/thread/step: ~40 crossbar cyc/warp and
// ~288 LSU-issue cyc/SMSP, both hidden under the 512-cyc FMA issue floor.
// h kept as packed float2 in SMEM with 17-pair chunk stride (conflict-free).
// Thread (q = tid&7, jset = tid>>3) covers outputs jset*4..+3, k-chunk q*32..+31.
// =============================================================================
__global__ __launch_bounds__(512, 1) void rnn_scan(
    const float* __restrict__ W, const float* __restrict__ hidden,
    float* __restrict__ out)
{
    extern __shared__ u64 dynsm[];
    u64*   resw = dynsm;                     // [20][512] u64         (81920 B)
    float* part = (float*)(dynsm + 10240);   // [256*9] floats         (9216 B)
    u64*   h2   = dynsm + 11392;             // [2][8*17] u64 (padded) (2176 B)

    const int tid  = threadIdx.x;
    const int b    = blockIdx.x;
    const int q    = tid & 7;
    const int jset = tid >> 3;

    // ---- load weights: 11 reg pairs + 5 residual pairs per (output, chunk) ----
    u64 w[4][11];
    #pragma unroll
    for (int u = 0; u < 4; u++) {
        const u64* wr = (const u64*)(W + (size_t)(jset * 4 + u) * 512 + 256);
        #pragma unroll
        for (int i = 0; i < 11; i++) w[u][i] = wr[q * 16 + i];
        #pragma unroll
        for (int ir = 0; ir < 5; ir++)
            resw[(u * 5 + ir) * 512 + tid] = wr[q * 16 + 11 + ir];
    }

    // ---- init h (buffer 0) from `hidden` input ----
    if (tid < 128) {
        u64 hv = ((const u64*)(hidden + b * 256))[tid];
        h2[(tid >> 4) * 17 + (tid & 15)] = hv;
    }

    // ---- prefetch xproj[b,0,tid] (xproj staged in `out`) ----
    float xpre = 0.f;
    float* outp = out + (size_t)b * 2048 * 256 + tid;
    if (tid < 256) xpre = *outp;

    __syncthreads();

    const u64* rw = resw + tid;

    #pragma unroll 1
    for (int t = 0; t < 2048; t++) {
        const u64* hb = h2 + (t & 1) * 136 + q * 17;
        u64 a0 = 0, a1 = 0, a2 = 0, a3 = 0;
        #pragma unroll
        for (int i = 0; i < 11; i++) {
            u64 hh = hb[i];
            a0 = ffma2(w[0][i], hh, a0);
            a1 = ffma2(w[1][i], hh, a1);
            a2 = ffma2(w[2][i], hh, a2);
            a3 = ffma2(w[3][i], hh, a3);
        }
        #pragma unroll
        for (int ir = 0; ir < 5; ir++) {
            u64 hh = hb[11 + ir];
            a0 = ffma2(rw[(0 * 5 + ir) * 512], hh, a0);
            a1 = ffma2(rw[(1 * 5 + ir) * 512], hh, a1);
            a2 = ffma2(rw[(2 * 5 + ir) * 512], hh, a2);
            a3 = ffma2(rw[(3 * 5 + ir) * 512], hh, a3);
        }
        float2 f0 = unpack2(a0), f1 = unpack2(a1), f2 = unpack2(a2), f3 = unpack2(a3);
        const int pb = (jset * 4) * 9 + q;
        part[pb]      = f0.x + f0.y;
        part[pb + 9]  = f1.x + f1.y;
        part[pb + 18] = f2.x + f2.y;
        part[pb + 27] = f3.x + f3.y;
        __syncthreads();
        if (tid < 256) {
            const float* pr = part + tid * 9;
            float s = ((pr[0] + pr[1]) + (pr[2] + pr[3]))
                    + ((pr[4] + pr[5]) + (pr[6] + pr[7]));
            float hnew = s + xpre;
            int p = tid >> 1;
            float* hw = (float*)(h2 + ((t + 1) & 1) * 136);
            hw[((p >> 4) * 17 + (p & 15)) * 2 + (tid & 1)] = hnew;
            *outp = hnew;
            if (t < 2047) xpre = outp[256];
            outp += 256;
        }
        __syncthreads();
    }
}

// =============================================================================
extern "C" void kernel_launch(void* const* d_in, const int* in_sizes, int n_in,
                              void* d_out, int out_size)
{
    (void)in_sizes; (void)n_in; (void)out_size;
    const float* X      = (const float*)d_in[0];   // input_seq [64,2048,256]
    const float* hidden = (const float*)d_in[1];   // [64,256]
    const float* W      = (const float*)d_in[2];   // [256,512]
    const float* bias   = (const float*)d_in[3];   // [256]
    float* out          = (float*)d_out;           // [64,2048,256]

    // Phase 1: x_proj into d_out (scratch-in-place).
    dim3 g1(1024, 2);
    xproj_gemm<<<g1, 256>>>(X, W, bias, out);

    // Phase 2: sequential scan, 64 CTAs (one per batch), 93312 B dynamic smem.
    cudaFuncSetAttribute(rnn_scan, cudaFuncAttributeMaxDynamicSharedMemorySize, 93312);
    rnn_scan<<<64, 512, 93312>>>(W, hidden, out);
}